// round 15
// baseline (speedup 1.0000x reference)
#include <cuda_runtime.h>
#include <cuda_bf16.h>
#include <cstdint>

#if defined(__CUDA_ARCH_FEAT_SM103_ALL) || \
    (defined(__CUDA_ARCH_SPECIFIC__) && (__CUDA_ARCH_SPECIFIC__ == 1030))
#define HAS_TCGEN05 1
#else
#define HAS_TCGEN05 0
#endif

constexpr int B_  = 32;
constexpr int C_  = 2048;
constexpr int H_  = 48;
constexpr int W_  = 24;
constexpr int P_  = 3;
constexpr int IC_ = 128;
constexpr int C4_ = 512;
constexpr int PH_ = 16;
constexpr int HD_ = 8;
constexpr int WD_ = 12;
constexpr int N_  = 96;
constexpr int BN_ = B_ * N_;   // 3072

// ---------------- static scratch ----------------
__device__ __align__(128) __nv_bfloat16 g_Wq[P_ * IC_ * C_];
__device__ __align__(128) __nv_bfloat16 g_Wk[P_ * IC_ * C_];
__device__ float g_qbias[P_ * IC_];
__device__ float g_kbias[P_ * IC_];
__device__ __align__(128) __nv_bfloat16 g_Wv[(size_t)P_ * C_ * C_];
__device__ __align__(128) __nv_bfloat16 g_Wfc1[(size_t)P_ * C4_ * C_];
__device__ __align__(128) __nv_bfloat16 g_Wfc2[(size_t)P_ * C_ * C4_];
__device__ __align__(128) __nv_bfloat16 g_Xd[(size_t)P_ * C_ * BN_ + 128];
__device__ __align__(128) __nv_bfloat16 g_XdT[(size_t)P_ * BN_ * C_];
__device__ float g_meanXd[B_ * P_ * C_];
__device__ __align__(128) __nv_bfloat16 g_QT[(size_t)P_ * BN_ * IC_];
__device__ __align__(128) __nv_bfloat16 g_KT[(size_t)P_ * BN_ * IC_];
__device__ __align__(128) __nv_bfloat16 g_attn[(size_t)B_ * P_ * N_ * N_];
__device__ __align__(128) __nv_bfloat16 g_MT[(size_t)P_ * BN_ * C_];
__device__ __align__(128) __nv_bfloat16 g_AOT[(size_t)P_ * BN_ * C_];
__device__ __align__(128) __nv_bfloat16 g_gap[P_ * B_ * C_];
__device__ __align__(128) __nv_bfloat16 g_h1[P_ * B_ * C4_];
__device__ float g_cw[B_ * P_ * C_];

// ============ prep kernels ============
__global__ void fold_qk_kernel(const float* __restrict__ qw, const float* __restrict__ dwqw,
                               const float* __restrict__ dwqb, const float* __restrict__ qb,
                               const float* __restrict__ kw, const float* __restrict__ dwkw,
                               const float* __restrict__ dwkb, const float* __restrict__ kb) {
    int z = blockIdx.x;
    int s = (z >= P_ * IC_) ? 1 : 0;
    int pi = s ? (z - P_ * IC_) : z;
    int p = pi / IC_, i = pi % IC_;
    const float* Wsrc = s ? kw : qw;
    const float* dW = s ? dwkw : dwqw;
    const float* dB = s ? dwkb : dwqb;
    const float* Bz = s ? kb : qb;
    __nv_bfloat16* Wo = s ? g_Wk : g_Wq;
    float* bo = s ? g_kbias : g_qbias;
    int t = threadIdx.x;
    size_t wbase = ((size_t)p * IC_ + i) * C_;
    float accb = 0.f;
    for (int c = t; c < C_; c += 256) {
        float w = Wsrc[wbase + c];
        Wo[wbase + c] = __float2bfloat16(w * dW[p * C_ + c]);
        accb += w * dB[p * C_ + c];
    }
    __shared__ float red[256];
    red[t] = accb;
    __syncthreads();
    for (int o = 128; o > 0; o >>= 1) { if (t < o) red[t] += red[t + o]; __syncthreads(); }
    if (t == 0) bo[p * IC_ + i] = Bz[p * IC_ + i] + red[0];
}

__global__ void conv_weights_kernel(const float* __restrict__ vw,
                                    const float* __restrict__ f1,
                                    const float* __restrict__ f2) {
    size_t stride = (size_t)gridDim.x * blockDim.x;
    size_t i0 = (size_t)blockIdx.x * blockDim.x + threadIdx.x;
    size_t tv = (size_t)P_ * C_ * C_;
    for (size_t i = i0; i < tv; i += stride) g_Wv[i] = __float2bfloat16(vw[i]);
    size_t t1 = (size_t)P_ * C4_ * C_;
    for (size_t i = i0; i < t1; i += stride) g_Wfc1[i] = __float2bfloat16(f1[i]);
    for (size_t i = i0; i < t1; i += stride) g_Wfc2[i] = __float2bfloat16(f2[i]);
}

// ---------------- pool ----------------
__global__ void __launch_bounds__(288) pool_kernel(const float* __restrict__ x) {
    int bc = blockIdx.x;
    int b = bc / C_, c = bc % C_;
    int t = threadIdx.x;
    int p = t / N_, n = t % N_;
    int hd = n / WD_, wd = n % WD_;
    size_t base = (size_t)bc * (H_ * W_);
    int i0 = (p * PH_ + 2 * hd) * W_ + 2 * wd;
    float2 r0 = *reinterpret_cast<const float2*>(x + base + i0);
    float2 r1 = *reinterpret_cast<const float2*>(x + base + i0 + W_);
    float v = 0.25f * (r0.x + r0.y + r1.x + r1.y);
    g_Xd[((size_t)p * C_ + c) * BN_ + b * N_ + n] = __float2bfloat16(v);
    __shared__ float s[P_ * N_];
    s[t] = v;
    __syncthreads();
    if (t < P_) {
        float acc = 0.f;
        #pragma unroll 8
        for (int i = 0; i < N_; i++) acc += s[t * N_ + i];
        g_meanXd[((size_t)b * P_ + t) * C_ + c] = acc * (1.f / N_);
    }
}

// ---------------- transpose ----------------
__global__ void __launch_bounds__(256) transpose_xd_kernel() {
    __shared__ __nv_bfloat16 s[64][68];
    int p = blockIdx.z;
    int c0 = blockIdx.y * 64, n0 = blockIdx.x * 64;
    int t = threadIdx.x;
    int cr = t >> 4;
    int nc = (t & 15) * 4;
    const __nv_bfloat16* src = g_Xd + (size_t)p * C_ * BN_;
    #pragma unroll
    for (int j = 0; j < 64; j += 16) {
        uint64_t v = *reinterpret_cast<const uint64_t*>(
            src + (size_t)(c0 + cr + j) * BN_ + n0 + nc);
        const __nv_bfloat16* h = reinterpret_cast<const __nv_bfloat16*>(&v);
        #pragma unroll
        for (int i = 0; i < 4; i++) s[nc + i][cr + j] = h[i];
    }
    __syncthreads();
    __nv_bfloat16* dst = g_XdT + (size_t)p * BN_ * C_;
    int nr = t >> 4;
    int cc = (t & 15) * 4;
    #pragma unroll
    for (int j = 0; j < 64; j += 16) {
        uint64_t v = *reinterpret_cast<const uint64_t*>(&s[nr + j][cc]);
        *reinterpret_cast<uint64_t*>(dst + (size_t)(n0 + nr + j) * C_ + c0 + cc) = v;
    }
}

// ============ HMMA building blocks ============
__device__ __forceinline__ void mma16816(float* d, const uint32_t* a, const uint32_t* b) {
    asm volatile(
        "mma.sync.aligned.m16n8k16.row.col.f32.bf16.bf16.f32 "
        "{%0,%1,%2,%3}, {%4,%5,%6,%7}, {%8,%9}, {%0,%1,%2,%3};\n"
        : "+f"(d[0]), "+f"(d[1]), "+f"(d[2]), "+f"(d[3])
        : "r"(a[0]), "r"(a[1]), "r"(a[2]), "r"(a[3]), "r"(b[0]), "r"(b[1]));
}

constexpr int TSTR = 40;
constexpr int MODE_F32 = 0, MODE_BF16 = 1, MODE_RELU_BF16 = 2, MODE_SIG_F32 = 3;

__device__ __forceinline__ void ldst_tile(int tid, __nv_bfloat16* dst,
                                          const __nv_bfloat16* src, int ld, int rows_valid) {
    #pragma unroll
    for (int it = 0; it < 4; it++) {
        int u = tid + it * 256;
        int row = u >> 3, ck = u & 7;
        const __nv_bfloat16* g = src + (size_t)row * ld + (ck << 2);
        uint32_t s = (uint32_t)__cvta_generic_to_shared(dst + row * TSTR + (ck << 2));
        int sz = (row < rows_valid) ? 8 : 0;
        asm volatile("cp.async.ca.shared.global [%0], [%1], 8, %2;\n"
                     :: "r"(s), "l"(g), "r"(sz));
    }
}

template <int MODE>
__device__ __forceinline__ void gemm_cp_body(
    __nv_bfloat16* smA, __nv_bfloat16* smB,
    const __nv_bfloat16* __restrict__ A, int lda, int a_rows,
    const __nv_bfloat16* __restrict__ Bt, int ldb,
    void* __restrict__ Cout, int ldc,
    int K, const float* __restrict__ colbias) {
    int tid = threadIdx.x, lane = tid & 31, warp = tid >> 5;
    int wm = (warp >> 2) << 6;
    int wn = (warp & 3) << 5;

    float acc[4][4][4];
    #pragma unroll
    for (int i = 0; i < 4; i++)
        #pragma unroll
        for (int j = 0; j < 4; j++)
            #pragma unroll
            for (int k = 0; k < 4; k++) acc[i][j][k] = 0.f;

    int nit = K >> 5;
    ldst_tile(tid, smA, A, lda, a_rows);
    ldst_tile(tid, smB, Bt, ldb, 128);
    asm volatile("cp.async.commit_group;\n");

    for (int it = 0; it < nit; it++) {
        if (it + 1 < nit) {
            int k0 = (it + 1) << 5;
            ldst_tile(tid, smA + ((it + 1) & 1) * 128 * TSTR, A + k0, lda, a_rows);
            ldst_tile(tid, smB + ((it + 1) & 1) * 128 * TSTR, Bt + k0, ldb, 128);
            asm volatile("cp.async.commit_group;\n");
            asm volatile("cp.async.wait_group 1;\n");
        } else {
            asm volatile("cp.async.wait_group 0;\n");
        }
        __syncthreads();
        const __nv_bfloat16* As = smA + (it & 1) * 128 * TSTR;
        const __nv_bfloat16* Bs = smB + (it & 1) * 128 * TSTR;
        #pragma unroll
        for (int ks = 0; ks < 32; ks += 16) {
            uint32_t af[4][4], bfr[4][2];
            int ar = lane >> 2;
            int ac = ks + ((lane & 3) << 1);
            #pragma unroll
            for (int mi = 0; mi < 4; mi++) {
                int r = wm + (mi << 4) + ar;
                af[mi][0] = *(const uint32_t*)(As + r * TSTR + ac);
                af[mi][1] = *(const uint32_t*)(As + (r + 8) * TSTR + ac);
                af[mi][2] = *(const uint32_t*)(As + r * TSTR + ac + 8);
                af[mi][3] = *(const uint32_t*)(As + (r + 8) * TSTR + ac + 8);
            }
            #pragma unroll
            for (int ni = 0; ni < 4; ni++) {
                int nr = wn + (ni << 3) + ar;
                bfr[ni][0] = *(const uint32_t*)(Bs + nr * TSTR + ac);
                bfr[ni][1] = *(const uint32_t*)(Bs + nr * TSTR + ac + 8);
            }
            #pragma unroll
            for (int mi = 0; mi < 4; mi++)
                #pragma unroll
                for (int ni = 0; ni < 4; ni++) mma16816(acc[mi][ni], af[mi], bfr[ni]);
        }
        __syncthreads();
    }

    #pragma unroll
    for (int mi = 0; mi < 4; mi++) {
        int r = wm + (mi << 4) + (lane >> 2);
        bool gr0 = r < a_rows;
        bool gr1 = (r + 8) < a_rows;
        #pragma unroll
        for (int ni = 0; ni < 4; ni++) {
            int cc = wn + (ni << 3) + ((lane & 3) << 1);
            float b0 = colbias ? colbias[cc] : 0.f;
            float b1 = colbias ? colbias[cc + 1] : 0.f;
            float x0 = acc[mi][ni][0] + b0, x1 = acc[mi][ni][1] + b1;
            float y0 = acc[mi][ni][2] + b0, y1 = acc[mi][ni][3] + b1;
            if constexpr (MODE == MODE_RELU_BF16) {
                x0 = fmaxf(x0, 0.f); x1 = fmaxf(x1, 0.f);
                y0 = fmaxf(y0, 0.f); y1 = fmaxf(y1, 0.f);
            }
            if constexpr (MODE == MODE_SIG_F32) {
                x0 = 1.f / (1.f + expf(-x0)); x1 = 1.f / (1.f + expf(-x1));
                y0 = 1.f / (1.f + expf(-y0)); y1 = 1.f / (1.f + expf(-y1));
            }
            if constexpr (MODE == MODE_BF16 || MODE == MODE_RELU_BF16) {
                __nv_bfloat16* Cp = (__nv_bfloat16*)Cout;
                __nv_bfloat162 v0, v1;
                v0.x = __float2bfloat16(x0); v0.y = __float2bfloat16(x1);
                v1.x = __float2bfloat16(y0); v1.y = __float2bfloat16(y1);
                if (gr0) *reinterpret_cast<__nv_bfloat162*>(Cp + (size_t)r * ldc + cc) = v0;
                if (gr1) *reinterpret_cast<__nv_bfloat162*>(Cp + (size_t)(r + 8) * ldc + cc) = v1;
            } else {
                float* Cp = (float*)Cout;
                if (gr0) *reinterpret_cast<float2*>(Cp + (size_t)r * ldc + cc) = make_float2(x0, x1);
                if (gr1) *reinterpret_cast<float2*>(Cp + (size_t)(r + 8) * ldc + cc) = make_float2(y0, y1);
            }
        }
    }
}

// ============ tcgen05 GEMM ============
constexpr uint64_t DESC_BASE_SW128 =
    (uint64_t(2) << 61) | (uint64_t(1) << 46) | (uint64_t(64) << 32) | (uint64_t(1) << 16);
constexpr int TC_SMEM = 99328;
constexpr int TC_SMEM_V = 132096;   // 2 stages x (A1 16K + A2 16K + B 32K) + align

__device__ __forceinline__ uint32_t smem_u32(const void* p) {
    return (uint32_t)__cvta_generic_to_shared(p);
}

#if HAS_TCGEN05
__device__ __forceinline__ void mbar_wait_par(uint32_t addr, uint32_t parity) {
    asm volatile(
        "{\n\t.reg .pred P1;\n\t"
        "LAB_%=: mbarrier.try_wait.parity.acquire.cta.shared::cta.b64 P1, [%0], %1, 0x989680;\n\t"
        "@!P1 bra LAB_%=;\n\t}"
        :: "r"(addr), "r"(parity) : "memory");
}

__device__ __forceinline__ void mma_f16_ss_cg1(uint32_t d, uint64_t ad, uint64_t bd,
                                               uint32_t idesc, uint32_t en) {
    asm volatile(
        "{\n\t.reg .pred p;\n\tsetp.ne.u32 p, %5, 0;\n\t"
        "tcgen05.mma.cta_group::1.kind::f16 [%0], %1, %2, %3, {%4,%4,%4,%4}, p;\n\t}"
        :: "r"(d), "l"(ad), "l"(bd), "r"(idesc), "r"(0u), "r"(en) : "memory");
}

__device__ __forceinline__ void ldtm_x32(uint32_t* r, uint32_t addr) {
    asm volatile(
        "tcgen05.ld.sync.aligned.32x32b.x32.b32 "
        "{%0,%1,%2,%3,%4,%5,%6,%7,%8,%9,%10,%11,%12,%13,%14,%15,"
        "%16,%17,%18,%19,%20,%21,%22,%23,%24,%25,%26,%27,%28,%29,%30,%31}, [%32];"
        : "=r"(r[0]), "=r"(r[1]), "=r"(r[2]), "=r"(r[3]), "=r"(r[4]), "=r"(r[5]),
          "=r"(r[6]), "=r"(r[7]), "=r"(r[8]), "=r"(r[9]), "=r"(r[10]), "=r"(r[11]),
          "=r"(r[12]), "=r"(r[13]), "=r"(r[14]), "=r"(r[15]), "=r"(r[16]), "=r"(r[17]),
          "=r"(r[18]), "=r"(r[19]), "=r"(r[20]), "=r"(r[21]), "=r"(r[22]), "=r"(r[23]),
          "=r"(r[24]), "=r"(r[25]), "=r"(r[26]), "=r"(r[27]), "=r"(r[28]), "=r"(r[29]),
          "=r"(r[30]), "=r"(r[31])
        : "r"(addr));
}

template <int ROWS>
__device__ __forceinline__ void tc_load_tile(int tid, uint32_t sbase,
                                             const __nv_bfloat16* src, int ld, int k0) {
    #pragma unroll
    for (int it = 0; it < ROWS / 32; it++) {
        int u = tid + it * 256;
        int row = u >> 3, c16 = u & 7;
        const void* g = src + (size_t)row * ld + k0 + c16 * 8;
        uint32_t off = row * 128 + c16 * 16;
        uint32_t sw = off ^ ((off >> 3) & 0x70);
        asm volatile("cp.async.cg.shared.global [%0], [%1], 16;\n"
                     :: "r"(sbase + sw), "l"(g) : "memory");
    }
}
#endif

template <int NT, int STAGES, bool OUT_BF16>
__device__ void gemm_tc_body(const __nv_bfloat16* __restrict__ A, int lda,
                             const __nv_bfloat16* __restrict__ Bt, int ldb,
                             void* __restrict__ Cout, int ldc, int K,
                             const float* __restrict__ colbias) {
    extern __shared__ char dsm[];
#if HAS_TCGEN05
    constexpr int A_BYTES = 16384;
    constexpr int STAGE_BYTES = A_BYTES + NT * 128;
    constexpr uint32_t IDESC = (1u << 4) | (1u << 7) | (1u << 10) |
                               ((uint32_t)(NT / 8) << 17) | (8u << 24);
    __shared__ uint64_t s_mbar[STAGES];
    __shared__ uint32_t s_tptr;
    __shared__ float biass[NT];
    int tid = threadIdx.x;
    uint32_t base = (smem_u32(dsm) + 1023) & ~1023u;

    if (tid < 32) {
        asm volatile("tcgen05.alloc.cta_group::1.sync.aligned.shared::cta.b32 [%0], %1;"
                     :: "r"(smem_u32(&s_tptr)), "r"(NT) : "memory");
        asm volatile("tcgen05.relinquish_alloc_permit.cta_group::1.sync.aligned;" ::: "memory");
    }
    if (tid == 0) {
        #pragma unroll
        for (int i = 0; i < STAGES; i++)
            asm volatile("mbarrier.init.shared.b64 [%0], 1;"
                         :: "r"(smem_u32(&s_mbar[i])) : "memory");
    }
    #pragma unroll
    for (int i = tid; i < NT; i += 256) biass[i] = colbias ? colbias[i] : 0.f;
    __syncthreads();
    uint32_t tmem = s_tptr;
    const int S = K >> 6;

    #pragma unroll
    for (int st = 0; st < STAGES - 1; st++) {
        tc_load_tile<128>(tid, base + st * STAGE_BYTES, A, lda, st * 64);
        tc_load_tile<NT>(tid, base + st * STAGE_BYTES + A_BYTES, Bt, ldb, st * 64);
        asm volatile("cp.async.commit_group;\n" ::: "memory");
    }

    for (int s = 0; s < S; s++) {
        if (s + STAGES - 1 < S) {
            if (s >= 1) {
                int u = s - 1;
                mbar_wait_par(smem_u32(&s_mbar[u % STAGES]), (uint32_t)((u / STAGES) & 1));
            }
            int b = (s + STAGES - 1) % STAGES;
            tc_load_tile<128>(tid, base + b * STAGE_BYTES, A, lda, (s + STAGES - 1) * 64);
            tc_load_tile<NT>(tid, base + b * STAGE_BYTES + A_BYTES, Bt, ldb,
                             (s + STAGES - 1) * 64);
        }
        asm volatile("cp.async.commit_group;\n" ::: "memory");
        asm volatile("cp.async.wait_group %0;\n" :: "n"(STAGES - 1) : "memory");
        __syncthreads();
        asm volatile("fence.proxy.async.shared::cta;" ::: "memory");
        if (tid == 0) {
            int b = s % STAGES;
            uint64_t ad = DESC_BASE_SW128 |
                          ((uint64_t)((base + b * STAGE_BYTES) >> 4) & 0x3FFF);
            uint64_t bd = DESC_BASE_SW128 |
                          ((uint64_t)((base + b * STAGE_BYTES + A_BYTES) >> 4) & 0x3FFF);
            #pragma unroll
            for (int q = 0; q < 4; q++)
                mma_f16_ss_cg1(tmem, ad + q * 2, bd + q * 2, IDESC,
                               (s > 0 || q > 0) ? 1u : 0u);
            asm volatile(
                "tcgen05.commit.cta_group::1.mbarrier::arrive::one.shared::cluster.b64 [%0];"
                :: "r"(smem_u32(&s_mbar[b])) : "memory");
        }
    }
    {
        int u = S - 1;
        mbar_wait_par(smem_u32(&s_mbar[u % STAGES]), (uint32_t)((u / STAGES) & 1));
    }
    asm volatile("tcgen05.fence::after_thread_sync;" ::: "memory");

    int w = tid >> 5, lane = tid & 31;
    int row = (w & 3) * 32 + lane;
    int colbase = (w >> 2) * (NT / 2);

    if constexpr (OUT_BF16) {
        constexpr int OSTR = NT + 24;
        __nv_bfloat16* so = (__nv_bfloat16*)(dsm + (base - smem_u32(dsm)));
        __syncthreads();
        #pragma unroll
        for (int half = 0; half < NT / 64; half++) {
            int cb = colbase + half * 32;
            uint32_t r[32];
            ldtm_x32(r, tmem + cb);
            asm volatile("tcgen05.wait::ld.sync.aligned;" ::: "memory");
            #pragma unroll
            for (int j = 0; j < 32; j += 2) {
                __nv_bfloat162 h;
                h.x = __float2bfloat16(__uint_as_float(r[j]) + biass[cb + j]);
                h.y = __float2bfloat16(__uint_as_float(r[j + 1]) + biass[cb + j + 1]);
                *reinterpret_cast<__nv_bfloat162*>(so + row * OSTR + cb + j) = h;
            }
        }
        __syncthreads();
        constexpr int CH = NT / 8;
        __nv_bfloat16* Cp = (__nv_bfloat16*)Cout;
        #pragma unroll
        for (int u = tid; u < 128 * CH; u += 256) {
            int rr = u / CH, cc = (u - rr * CH) * 8;
            uint4 v = *reinterpret_cast<const uint4*>(so + rr * OSTR + cc);
            *reinterpret_cast<uint4*>(Cp + (size_t)rr * ldc + cc) = v;
        }
    } else {
        #pragma unroll
        for (int half = 0; half < NT / 64; half++) {
            int cb = colbase + half * 32;
            uint32_t r[32];
            ldtm_x32(r, tmem + cb);
            asm volatile("tcgen05.wait::ld.sync.aligned;" ::: "memory");
            float* Cp = (float*)Cout;
            #pragma unroll
            for (int j = 0; j < 32; j += 4) {
                float4 v;
                v.x = __uint_as_float(r[j]) + biass[cb + j];
                v.y = __uint_as_float(r[j + 1]) + biass[cb + j + 1];
                v.z = __uint_as_float(r[j + 2]) + biass[cb + j + 2];
                v.w = __uint_as_float(r[j + 3]) + biass[cb + j + 3];
                *reinterpret_cast<float4*>(Cp + (size_t)row * ldc + cb + j) = v;
            }
        }
    }
    __syncthreads();
    if (tid < 32)
        asm volatile("tcgen05.dealloc.cta_group::1.sync.aligned.b32 %0, %1;"
                     :: "r"(tmem), "r"(NT));
#else
    __nv_bfloat16* smA = (__nv_bfloat16*)dsm;
    __nv_bfloat16* smB = smA + 2 * 128 * TSTR;
    #pragma unroll
    for (int nt2 = 0; nt2 < NT / 128; nt2++) {
        if (nt2 > 0) __syncthreads();
        if constexpr (OUT_BF16)
            gemm_cp_body<MODE_BF16>(smA, smB, A, lda, 128, Bt + (size_t)nt2 * 128 * ldb, ldb,
                                    (__nv_bfloat16*)Cout + nt2 * 128, ldc, K,
                                    colbias ? colbias + nt2 * 128 : nullptr);
        else
            gemm_cp_body<MODE_F32>(smA, smB, A, lda, 128, Bt + (size_t)nt2 * 128 * ldb, ldb,
                                   (float*)Cout + nt2 * 128, ldc, K,
                                   colbias ? colbias + nt2 * 128 : nullptr);
    }
#endif
}

__global__ void __launch_bounds__(256) gemm_qk_tc_kernel() {
    int z = blockIdx.z;
    int p = z >> 1, s = z & 1;
    const __nv_bfloat16* A = g_XdT + ((size_t)p * BN_ + (size_t)blockIdx.x * 128) * C_;
    const __nv_bfloat16* Bt = (s ? g_Wk : g_Wq) + (size_t)p * IC_ * C_;
    __nv_bfloat16* Cm = (s ? g_KT : g_QT) + ((size_t)p * BN_ + (size_t)blockIdx.x * 128) * IC_;
    const float* cb = (s ? g_kbias : g_qbias) + p * IC_;
    gemm_tc_body<128, 3, true>(A, C_, Bt, C_, Cm, IC_, C_, cb);
}

// ---------------- V-GEMM: M=256 (two TMEM accumulators), N=256, shared B ----------------
__global__ void __launch_bounds__(256) gemm_v_tc2_kernel(const float* __restrict__ vb) {
    extern __shared__ char dsm[];
#if HAS_TCGEN05
    constexpr int STAGE_BYTES = 65536;  // A1 16K | A2 16K | B 32K
    constexpr uint32_t IDESC = (1u << 4) | (1u << 7) | (1u << 10) |
                               (32u << 17) | (8u << 24);   // N=256, M=128
    __shared__ uint64_t s_mbar[2];
    __shared__ uint32_t s_tptr;
    __shared__ float biass[256];
    int tid = threadIdx.x;
    int p = blockIdx.z;
    const __nv_bfloat16* A = g_MT + ((size_t)p * BN_ + (size_t)blockIdx.x * 256) * C_;
    const __nv_bfloat16* Bt = g_Wv + ((size_t)p * C_ + (size_t)blockIdx.y * 256) * C_;
    __nv_bfloat16* Cm = g_AOT + ((size_t)p * BN_ + (size_t)blockIdx.x * 256) * C_ + blockIdx.y * 256;
    const float* colbias = vb + p * C_ + blockIdx.y * 256;
    uint32_t base = (smem_u32(dsm) + 1023) & ~1023u;

    if (tid < 32) {
        asm volatile("tcgen05.alloc.cta_group::1.sync.aligned.shared::cta.b32 [%0], %1;"
                     :: "r"(smem_u32(&s_tptr)), "r"(512) : "memory");
        asm volatile("tcgen05.relinquish_alloc_permit.cta_group::1.sync.aligned;" ::: "memory");
    }
    if (tid == 0) {
        #pragma unroll
        for (int i = 0; i < 2; i++)
            asm volatile("mbarrier.init.shared.b64 [%0], 1;"
                         :: "r"(smem_u32(&s_mbar[i])) : "memory");
    }
    biass[tid] = colbias[tid];
    if (tid < 0) {}  // keep 256-thread layout explicit
    #pragma unroll
    for (int i = tid + 256; i < 256; i += 256) {}
    __syncthreads();
    uint32_t tmem = s_tptr;
    const int S = C_ >> 6;   // 32

    // prologue: stage 0
    tc_load_tile<128>(tid, base, A, C_, 0);
    tc_load_tile<128>(tid, base + 16384, A + (size_t)128 * C_, C_, 0);
    tc_load_tile<256>(tid, base + 32768, Bt, C_, 0);
    asm volatile("cp.async.commit_group;\n" ::: "memory");

    for (int s = 0; s < S; s++) {
        if (s + 1 < S) {
            if (s >= 1) {
                int u = s - 1;
                mbar_wait_par(smem_u32(&s_mbar[u & 1]), (uint32_t)((u >> 1) & 1));
            }
            int b = (s + 1) & 1;
            int k0 = (s + 1) * 64;
            tc_load_tile<128>(tid, base + b * STAGE_BYTES, A, C_, k0);
            tc_load_tile<128>(tid, base + b * STAGE_BYTES + 16384, A + (size_t)128 * C_, C_, k0);
            tc_load_tile<256>(tid, base + b * STAGE_BYTES + 32768, Bt, C_, k0);
        }
        asm volatile("cp.async.commit_group;\n" ::: "memory");
        asm volatile("cp.async.wait_group 1;\n" ::: "memory");
        __syncthreads();
        asm volatile("fence.proxy.async.shared::cta;" ::: "memory");
        if (tid == 0) {
            int b = s & 1;
            uint64_t ad1 = DESC_BASE_SW128 |
                           ((uint64_t)((base + b * STAGE_BYTES) >> 4) & 0x3FFF);
            uint64_t ad2 = DESC_BASE_SW128 |
                           ((uint64_t)((base + b * STAGE_BYTES + 16384) >> 4) & 0x3FFF);
            uint64_t bd = DESC_BASE_SW128 |
                          ((uint64_t)((base + b * STAGE_BYTES + 32768) >> 4) & 0x3FFF);
            #pragma unroll
            for (int q = 0; q < 4; q++)
                mma_f16_ss_cg1(tmem, ad1 + q * 2, bd + q * 2, IDESC,
                               (s > 0 || q > 0) ? 1u : 0u);
            #pragma unroll
            for (int q = 0; q < 4; q++)
                mma_f16_ss_cg1(tmem + 256, ad2 + q * 2, bd + q * 2, IDESC,
                               (s > 0 || q > 0) ? 1u : 0u);
            asm volatile(
                "tcgen05.commit.cta_group::1.mbarrier::arrive::one.shared::cluster.b64 [%0];"
                :: "r"(smem_u32(&s_mbar[b])) : "memory");
        }
    }
    {
        int u = S - 1;
        mbar_wait_par(smem_u32(&s_mbar[u & 1]), (uint32_t)((u >> 1) & 1));
    }
    asm volatile("tcgen05.fence::after_thread_sync;" ::: "memory");

    int w = tid >> 5, lane = tid & 31;
    int row = (w & 3) * 32 + lane;
    int colbase = (w >> 2) * 128;
    constexpr int OSTR = 280;
    __nv_bfloat16* so = (__nv_bfloat16*)(dsm + (base - smem_u32(dsm)));

    #pragma unroll
    for (int acc = 0; acc < 2; acc++) {
        __syncthreads();
        #pragma unroll
        for (int half = 0; half < 4; half++) {
            int cb = colbase + half * 32;
            uint32_t r[32];
            ldtm_x32(r, tmem + acc * 256 + cb);
            asm volatile("tcgen05.wait::ld.sync.aligned;" ::: "memory");
            #pragma unroll
            for (int j = 0; j < 32; j += 2) {
                __nv_bfloat162 h;
                h.x = __float2bfloat16(__uint_as_float(r[j]) + biass[cb + j]);
                h.y = __float2bfloat16(__uint_as_float(r[j + 1]) + biass[cb + j + 1]);
                *reinterpret_cast<__nv_bfloat162*>(so + row * OSTR + cb + j) = h;
            }
        }
        __syncthreads();
        #pragma unroll
        for (int u = tid; u < 128 * 32; u += 256) {
            int rr = u >> 5, cc = (u & 31) * 8;
            uint4 v = *reinterpret_cast<const uint4*>(so + rr * OSTR + cc);
            *reinterpret_cast<uint4*>(Cm + (size_t)(acc * 128 + rr) * C_ + cc) = v;
        }
    }
    __syncthreads();
    if (tid < 32)
        asm volatile("tcgen05.dealloc.cta_group::1.sync.aligned.b32 %0, %1;"
                     :: "r"(tmem), "r"(512));
#else
    __nv_bfloat16* smA = (__nv_bfloat16*)dsm;
    __nv_bfloat16* smB = smA + 2 * 128 * TSTR;
    int p = blockIdx.z;
    const __nv_bfloat16* A = g_MT + ((size_t)p * BN_ + (size_t)blockIdx.x * 256) * C_;
    const __nv_bfloat16* Bt = g_Wv + ((size_t)p * C_ + (size_t)blockIdx.y * 256) * C_;
    __nv_bfloat16* Cm = g_AOT + ((size_t)p * BN_ + (size_t)blockIdx.x * 256) * C_ + blockIdx.y * 256;
    const float* colbias = vb + p * C_ + blockIdx.y * 256;
    #pragma unroll
    for (int mt2 = 0; mt2 < 2; mt2++)
        #pragma unroll
        for (int nt2 = 0; nt2 < 2; nt2++) {
            if (mt2 > 0 || nt2 > 0) __syncthreads();
            gemm_cp_body<MODE_BF16>(smA, smB, A + (size_t)mt2 * 128 * C_, C_, 128,
                                    Bt + (size_t)nt2 * 128 * C_, C_,
                                    Cm + (size_t)mt2 * 128 * C_ + nt2 * 128, C_, C_,
                                    colbias + nt2 * 128);
        }
#endif
}

// MT via HMMA (K=96)
__global__ void __launch_bounds__(256, 2) gemm_m_kernel() {
    __shared__ __nv_bfloat16 smA[2][128 * TSTR];
    __shared__ __nv_bfloat16 smB[2][128 * TSTR];
    int z = blockIdx.z;
    int b = z / P_, p = z % P_;
    const __nv_bfloat16* A = g_attn + (size_t)z * N_ * N_;
    const __nv_bfloat16* Bt = g_Xd + ((size_t)p * C_ + (size_t)blockIdx.x * 128) * BN_ + b * N_;
    __nv_bfloat16* Cm = g_MT + ((size_t)p * BN_ + b * N_) * C_ + blockIdx.x * 128;
    gemm_cp_body<MODE_BF16>(&smA[0][0], &smB[0][0], A, N_, N_, Bt, BN_, Cm, C_, N_, nullptr);
}

// ---------------- attention ----------------
__global__ void __launch_bounds__(256) attn_kernel() {
    int bp = blockIdx.x;
    int b = bp / P_, p = bp % P_;
    __shared__ __nv_bfloat16 qs[IC_ * N_];
    __shared__ __nv_bfloat16 ks[IC_ * N_];
    int t = threadIdx.x;
    const __nv_bfloat16* qt = g_QT + ((size_t)p * BN_ + b * N_) * IC_;
    const __nv_bfloat16* kt = g_KT + ((size_t)p * BN_ + b * N_) * IC_;
    for (int u = t; u < IC_ * N_; u += 256) {
        int n = u >> 7, i = u & 127;
        qs[i * N_ + n] = qt[n * IC_ + i];
        ks[i * N_ + n] = kt[n * IC_ + i];
    }
    __syncthreads();
    int wid = t >> 5, lane = t & 31;
    size_t ab = (size_t)bp * N_ * N_;
    for (int n = wid; n < N_; n += 8) {
        float e0 = 0.f, e1 = 0.f, e2 = 0.f;
        for (int i = 0; i < IC_; i++) {
            float qv = __bfloat162float(qs[i * N_ + n]);
            e0 += qv * __bfloat162float(ks[i * N_ + lane]);
            e1 += qv * __bfloat162float(ks[i * N_ + lane + 32]);
            e2 += qv * __bfloat162float(ks[i * N_ + lane + 64]);
        }
        float mx = fmaxf(e0, fmaxf(e1, e2));
        #pragma unroll
        for (int o = 16; o; o >>= 1) mx = fmaxf(mx, __shfl_xor_sync(0xffffffffu, mx, o));
        float s0 = expf(e0 - mx), s1 = expf(e1 - mx), s2 = expf(e2 - mx);
        float ss = s0 + s1 + s2;
        #pragma unroll
        for (int o = 16; o; o >>= 1) ss += __shfl_xor_sync(0xffffffffu, ss, o);
        float inv = 1.f / ss;
        g_attn[ab + (size_t)n * N_ + lane] = __float2bfloat16(s0 * inv);
        g_attn[ab + (size_t)n * N_ + lane + 32] = __float2bfloat16(s1 * inv);
        g_attn[ab + (size_t)n * N_ + lane + 64] = __float2bfloat16(s2 * inv);
    }
}

// ---------------- gap reduce ----------------
__global__ void __launch_bounds__(512) gap_kernel(const float* __restrict__ pa_gamma) {
    int bp = blockIdx.x;
    int b = bp / P_, p = bp % P_;
    int t = threadIdx.x;
    float gam = pa_gamma[p];
    const __nv_bfloat16* aob = g_AOT + ((size_t)p * BN_ + b * N_) * C_;
    for (int c = t; c < C_; c += 512) {
        float acc = 0.f;
        #pragma unroll 8
        for (int n = 0; n < N_; n++) acc += __bfloat162float(aob[(size_t)n * C_ + c]);
        float g = gam * (acc * (1.f / N_)) + g_meanXd[((size_t)b * P_ + p) * C_ + c];
        g_gap[((size_t)p * B_ + b) * C_ + c] = __float2bfloat16(g);
    }
}

// ---------------- MLP ----------------
__global__ void __launch_bounds__(256) mlp1_kernel(const float* __restrict__ fc1b) {
    __shared__ __nv_bfloat16 smA[2][128 * TSTR];
    __shared__ __nv_bfloat16 smB[2][128 * TSTR];
    int p = blockIdx.z;
    const __nv_bfloat16* A = g_gap + (size_t)p * B_ * C_;
    const __nv_bfloat16* Bt = g_Wfc1 + ((size_t)p * C4_ + blockIdx.x * 128) * C_;
    __nv_bfloat16* Cm = g_h1 + (size_t)p * B_ * C4_ + blockIdx.x * 128;
    gemm_cp_body<MODE_RELU_BF16>(&smA[0][0], &smB[0][0], A, C_, B_, Bt, C_, Cm, C4_, C_,
                                 fc1b + p * C4_ + blockIdx.x * 128);
}

__global__ void __launch_bounds__(256) mlp2_kernel(const float* __restrict__ fc2b) {
    __shared__ __nv_bfloat16 smA[2][128 * TSTR];
    __shared__ __nv_bfloat16 smB[2][128 * TSTR];
    int p = blockIdx.z;
    const __nv_bfloat16* A = g_h1 + (size_t)p * B_ * C4_;
    const __nv_bfloat16* Bt = g_Wfc2 + ((size_t)p * C_ + blockIdx.x * 128) * C4_;
    float* Cm = g_cw + (size_t)p * C_ + blockIdx.x * 128;
    gemm_cp_body<MODE_SIG_F32>(&smA[0][0], &smB[0][0], A, C4_, B_, Bt, C4_, Cm, P_ * C_, C4_,
                               fc2b + p * C_ + blockIdx.x * 128);
}

// ---------------- fused upsample + pa/ca/gate + output ----------------
__global__ void __launch_bounds__(384) final_kernel(
    const float* __restrict__ x, float* __restrict__ out,
    const float* __restrict__ pa_gamma, const float* __restrict__ ca_gamma,
    const int* __restrict__ modality,
    const float* __restrict__ gw1, const float* __restrict__ gb1,
    const float* __restrict__ gw2, const float* __restrict__ gb2) {
    int cb = blockIdx.x;
    int p = blockIdx.y, b = blockIdx.z;
    __shared__ float aos[16][97];
    __shared__ float cws[16];
    int t = threadIdx.x;
    int c0 = cb * 16;
    const __nv_bfloat16* aob = g_AOT + ((size_t)p * BN_ + b * N_) * C_ + c0;
    for (int u = t; u < 16 * N_; u += 384) {
        int n = u >> 4, ch = u & 15;
        aos[ch][n] = __bfloat162float(aob[(size_t)n * C_ + ch]);
    }
    if (t < 16) cws[t] = g_cw[((size_t)b * P_ + p) * C_ + c0 + t];
    __syncthreads();

    float mf = (float)modality[b];
    float gacc = gb2[p];
    #pragma unroll
    for (int j = 0; j < 12; j++)
        gacc += fmaxf(mf * gw1[j] + gb1[j], 0.f) * gw2[p * 12 + j];
    float wgt = 1.f / (1.f + expf(-gacc));

    int ph = t / W_, w = t % W_;
    float srcr = 0.5f * ph - 0.25f;
    int ri = (int)floorf(srcr);
    float fr = srcr - ri;
    int ra = ri, rb = ri + 1;
    float wra = 1.f - fr, wrb = fr;
    if (ra < 0) { ra = 0; wra = 0.f; }
    if (rb > HD_ - 1) { rb = HD_ - 1; wrb = 0.f; }
    { float s = wra + wrb; wra /= s; wrb /= s; }
    float srcc = 0.5f * w - 0.25f;
    int ci = (int)floorf(srcc);
    float fc = srcc - ci;
    int ca = ci, cbx = ci + 1;
    float wca = 1.f - fc, wcb = fc;
    if (ca < 0) { ca = 0; wca = 0.f; }
    if (cbx > WD_ - 1) { cbx = WD_ - 1; wcb = 0.f; }
    { float s = wca + wcb; wca /= s; wcb /= s; }

    float pg = pa_gamma[p], cg = ca_gamma[p];

    #pragma unroll 4
    for (int ch = 0; ch < 16; ch++) {
        int c = c0 + ch;
        float up = wra * (wca * aos[ch][ra * WD_ + ca] + wcb * aos[ch][ra * WD_ + cbx]) +
                   wrb * (wca * aos[ch][rb * WD_ + ca] + wcb * aos[ch][rb * WD_ + cbx]);
        size_t xi = (((size_t)b * C_ + c) * H_ + p * PH_ + ph) * W_ + w;
        float xp = x[xi];
        float pa = pg * up + xp;
        float res = xp * (1.f - wgt) + wgt * pa * (1.f + cg * cws[ch]);
        out[xi] = res;
    }
}

extern "C" void kernel_launch(void* const* d_in, const int* in_sizes, int n_in,
                              void* d_out, int out_size) {
    const float* x = (const float*)d_in[0];
    cudaFuncSetAttribute(gemm_qk_tc_kernel, cudaFuncAttributeMaxDynamicSharedMemorySize, TC_SMEM);
    cudaFuncSetAttribute(gemm_v_tc2_kernel, cudaFuncAttributeMaxDynamicSharedMemorySize, TC_SMEM_V);

    fold_qk_kernel<<<2 * P_ * IC_, 256>>>(
        (const float*)d_in[3], (const float*)d_in[1], (const float*)d_in[2], (const float*)d_in[4],
        (const float*)d_in[7], (const float*)d_in[5], (const float*)d_in[6], (const float*)d_in[8]);
    conv_weights_kernel<<<4096, 256>>>((const float*)d_in[9],
                                       (const float*)d_in[12], (const float*)d_in[14]);
    pool_kernel<<<B_ * C_, 288>>>(x);
    transpose_xd_kernel<<<dim3(BN_ / 64, C_ / 64, P_), 256>>>();
    gemm_qk_tc_kernel<<<dim3(BN_ / 128, 1, 2 * P_), 256, TC_SMEM>>>();
    attn_kernel<<<B_ * P_, 256>>>();
    gemm_m_kernel<<<dim3(C_ / 128, 1, B_ * P_), 256>>>();
    gemm_v_tc2_kernel<<<dim3(BN_ / 256, C_ / 256, P_), 256, TC_SMEM_V>>>((const float*)d_in[10]);
    gap_kernel<<<B_ * P_, 512>>>((const float*)d_in[11]);
    mlp1_kernel<<<dim3(C4_ / 128, 1, P_), 256>>>((const float*)d_in[13]);
    mlp2_kernel<<<dim3(C_ / 128, 1, P_), 256>>>((const float*)d_in[15]);
    final_kernel<<<dim3(C_ / 16, P_, B_), 384>>>(x, (float*)d_out,
        (const float*)d_in[11], (const float*)d_in[16],
        (const int*)d_in[21],
        (const float*)d_in[17], (const float*)d_in[18],
        (const float*)d_in[19], (const float*)d_in[20]);
}

// round 16
// speedup vs baseline: 1.0491x; 1.0491x over previous
#include <cuda_runtime.h>
#include <cuda_bf16.h>
#include <cstdint>

#if defined(__CUDA_ARCH_FEAT_SM103_ALL) || \
    (defined(__CUDA_ARCH_SPECIFIC__) && (__CUDA_ARCH_SPECIFIC__ == 1030))
#define HAS_TCGEN05 1
#else
#define HAS_TCGEN05 0
#endif

constexpr int B_  = 32;
constexpr int C_  = 2048;
constexpr int H_  = 48;
constexpr int W_  = 24;
constexpr int P_  = 3;
constexpr int IC_ = 128;
constexpr int C4_ = 512;
constexpr int PH_ = 16;
constexpr int HD_ = 8;
constexpr int WD_ = 12;
constexpr int N_  = 96;
constexpr int BN_ = B_ * N_;   // 3072

// ---------------- static scratch ----------------
__device__ __align__(128) __nv_bfloat16 g_Wq[P_ * IC_ * C_];
__device__ __align__(128) __nv_bfloat16 g_Wk[P_ * IC_ * C_];
__device__ float g_qbias[P_ * IC_];
__device__ float g_kbias[P_ * IC_];
__device__ __align__(128) __nv_bfloat16 g_Wv[(size_t)P_ * C_ * C_];
__device__ __align__(128) __nv_bfloat16 g_Wfc1[(size_t)P_ * C4_ * C_];
__device__ __align__(128) __nv_bfloat16 g_Wfc2[(size_t)P_ * C_ * C4_];
__device__ __align__(128) __nv_bfloat16 g_Xd[(size_t)P_ * C_ * BN_ + 128];
__device__ __align__(128) __nv_bfloat16 g_XdT[(size_t)P_ * BN_ * C_];
__device__ float g_meanXd[B_ * P_ * C_];
__device__ __align__(128) __nv_bfloat16 g_QT[(size_t)P_ * BN_ * IC_];
__device__ __align__(128) __nv_bfloat16 g_KT[(size_t)P_ * BN_ * IC_];
__device__ __align__(128) __nv_bfloat16 g_attn[(size_t)B_ * P_ * N_ * N_];
__device__ __align__(128) __nv_bfloat16 g_MT[(size_t)P_ * BN_ * C_];
__device__ __align__(128) __nv_bfloat16 g_AOT[(size_t)P_ * BN_ * C_];
__device__ __align__(128) __nv_bfloat16 g_gap[P_ * B_ * C_];
__device__ __align__(128) __nv_bfloat16 g_h1[P_ * B_ * C4_];
__device__ float g_cw[B_ * P_ * C_];

// ============ prep kernels ============
__global__ void fold_qk_kernel(const float* __restrict__ qw, const float* __restrict__ dwqw,
                               const float* __restrict__ dwqb, const float* __restrict__ qb,
                               const float* __restrict__ kw, const float* __restrict__ dwkw,
                               const float* __restrict__ dwkb, const float* __restrict__ kb) {
    int z = blockIdx.x;
    int s = (z >= P_ * IC_) ? 1 : 0;
    int pi = s ? (z - P_ * IC_) : z;
    int p = pi / IC_, i = pi % IC_;
    const float* Wsrc = s ? kw : qw;
    const float* dW = s ? dwkw : dwqw;
    const float* dB = s ? dwkb : dwqb;
    const float* Bz = s ? kb : qb;
    __nv_bfloat16* Wo = s ? g_Wk : g_Wq;
    float* bo = s ? g_kbias : g_qbias;
    int t = threadIdx.x;
    size_t wbase = ((size_t)p * IC_ + i) * C_;
    float accb = 0.f;
    for (int c = t; c < C_; c += 256) {
        float w = Wsrc[wbase + c];
        Wo[wbase + c] = __float2bfloat16(w * dW[p * C_ + c]);
        accb += w * dB[p * C_ + c];
    }
    __shared__ float red[256];
    red[t] = accb;
    __syncthreads();
    for (int o = 128; o > 0; o >>= 1) { if (t < o) red[t] += red[t + o]; __syncthreads(); }
    if (t == 0) bo[p * IC_ + i] = Bz[p * IC_ + i] + red[0];
}

// vectorized fp32x4 -> bf16x4 conversion
__device__ __forceinline__ void conv4(const float* __restrict__ src,
                                      __nv_bfloat16* __restrict__ dst,
                                      size_t n4, size_t i0, size_t stride) {
    for (size_t i = i0; i < n4; i += stride) {
        float4 v = *reinterpret_cast<const float4*>(src + i * 4);
        __nv_bfloat16 h[4];
        h[0] = __float2bfloat16(v.x);
        h[1] = __float2bfloat16(v.y);
        h[2] = __float2bfloat16(v.z);
        h[3] = __float2bfloat16(v.w);
        *reinterpret_cast<uint64_t*>(dst + i * 4) = *reinterpret_cast<const uint64_t*>(h);
    }
}

__global__ void conv_weights_kernel(const float* __restrict__ vw,
                                    const float* __restrict__ f1,
                                    const float* __restrict__ f2) {
    size_t stride = (size_t)gridDim.x * blockDim.x;
    size_t i0 = (size_t)blockIdx.x * blockDim.x + threadIdx.x;
    conv4(vw, g_Wv, ((size_t)P_ * C_ * C_) / 4, i0, stride);
    conv4(f1, g_Wfc1, ((size_t)P_ * C4_ * C_) / 4, i0, stride);
    conv4(f2, g_Wfc2, ((size_t)P_ * C4_ * C_) / 4, i0, stride);
}

// ---------------- pool ----------------
__global__ void __launch_bounds__(288) pool_kernel(const float* __restrict__ x) {
    int bc = blockIdx.x;
    int b = bc / C_, c = bc % C_;
    int t = threadIdx.x;
    int p = t / N_, n = t % N_;
    int hd = n / WD_, wd = n % WD_;
    size_t base = (size_t)bc * (H_ * W_);
    int i0 = (p * PH_ + 2 * hd) * W_ + 2 * wd;
    float2 r0 = *reinterpret_cast<const float2*>(x + base + i0);
    float2 r1 = *reinterpret_cast<const float2*>(x + base + i0 + W_);
    float v = 0.25f * (r0.x + r0.y + r1.x + r1.y);
    g_Xd[((size_t)p * C_ + c) * BN_ + b * N_ + n] = __float2bfloat16(v);
    __shared__ float s[P_ * N_];
    s[t] = v;
    __syncthreads();
    if (t < P_) {
        float acc = 0.f;
        #pragma unroll 8
        for (int i = 0; i < N_; i++) acc += s[t * N_ + i];
        g_meanXd[((size_t)b * P_ + t) * C_ + c] = acc * (1.f / N_);
    }
}

// ---------------- transpose ----------------
__global__ void __launch_bounds__(256) transpose_xd_kernel() {
    __shared__ __nv_bfloat16 s[64][68];
    int p = blockIdx.z;
    int c0 = blockIdx.y * 64, n0 = blockIdx.x * 64;
    int t = threadIdx.x;
    int cr = t >> 4;
    int nc = (t & 15) * 4;
    const __nv_bfloat16* src = g_Xd + (size_t)p * C_ * BN_;
    #pragma unroll
    for (int j = 0; j < 64; j += 16) {
        uint64_t v = *reinterpret_cast<const uint64_t*>(
            src + (size_t)(c0 + cr + j) * BN_ + n0 + nc);
        const __nv_bfloat16* h = reinterpret_cast<const __nv_bfloat16*>(&v);
        #pragma unroll
        for (int i = 0; i < 4; i++) s[nc + i][cr + j] = h[i];
    }
    __syncthreads();
    __nv_bfloat16* dst = g_XdT + (size_t)p * BN_ * C_;
    int nr = t >> 4;
    int cc = (t & 15) * 4;
    #pragma unroll
    for (int j = 0; j < 64; j += 16) {
        uint64_t v = *reinterpret_cast<const uint64_t*>(&s[nr + j][cc]);
        *reinterpret_cast<uint64_t*>(dst + (size_t)(n0 + nr + j) * C_ + c0 + cc) = v;
    }
}

// ============ HMMA building blocks ============
__device__ __forceinline__ void mma16816(float* d, const uint32_t* a, const uint32_t* b) {
    asm volatile(
        "mma.sync.aligned.m16n8k16.row.col.f32.bf16.bf16.f32 "
        "{%0,%1,%2,%3}, {%4,%5,%6,%7}, {%8,%9}, {%0,%1,%2,%3};\n"
        : "+f"(d[0]), "+f"(d[1]), "+f"(d[2]), "+f"(d[3])
        : "r"(a[0]), "r"(a[1]), "r"(a[2]), "r"(a[3]), "r"(b[0]), "r"(b[1]));
}

constexpr int TSTR = 40;
constexpr int MODE_F32 = 0, MODE_BF16 = 1, MODE_RELU_BF16 = 2, MODE_SIG_F32 = 3;

__device__ __forceinline__ void ldst_tile(int tid, __nv_bfloat16* dst,
                                          const __nv_bfloat16* src, int ld, int rows_valid) {
    #pragma unroll
    for (int it = 0; it < 4; it++) {
        int u = tid + it * 256;
        int row = u >> 3, ck = u & 7;
        const __nv_bfloat16* g = src + (size_t)row * ld + (ck << 2);
        uint32_t s = (uint32_t)__cvta_generic_to_shared(dst + row * TSTR + (ck << 2));
        int sz = (row < rows_valid) ? 8 : 0;
        asm volatile("cp.async.ca.shared.global [%0], [%1], 8, %2;\n"
                     :: "r"(s), "l"(g), "r"(sz));
    }
}

template <int MODE>
__device__ __forceinline__ void gemm_cp_body(
    __nv_bfloat16* smA, __nv_bfloat16* smB,
    const __nv_bfloat16* __restrict__ A, int lda, int a_rows,
    const __nv_bfloat16* __restrict__ Bt, int ldb,
    void* __restrict__ Cout, int ldc,
    int K, const float* __restrict__ colbias) {
    int tid = threadIdx.x, lane = tid & 31, warp = tid >> 5;
    int wm = (warp >> 2) << 6;
    int wn = (warp & 3) << 5;

    float acc[4][4][4];
    #pragma unroll
    for (int i = 0; i < 4; i++)
        #pragma unroll
        for (int j = 0; j < 4; j++)
            #pragma unroll
            for (int k = 0; k < 4; k++) acc[i][j][k] = 0.f;

    int nit = K >> 5;
    ldst_tile(tid, smA, A, lda, a_rows);
    ldst_tile(tid, smB, Bt, ldb, 128);
    asm volatile("cp.async.commit_group;\n");

    for (int it = 0; it < nit; it++) {
        if (it + 1 < nit) {
            int k0 = (it + 1) << 5;
            ldst_tile(tid, smA + ((it + 1) & 1) * 128 * TSTR, A + k0, lda, a_rows);
            ldst_tile(tid, smB + ((it + 1) & 1) * 128 * TSTR, Bt + k0, ldb, 128);
            asm volatile("cp.async.commit_group;\n");
            asm volatile("cp.async.wait_group 1;\n");
        } else {
            asm volatile("cp.async.wait_group 0;\n");
        }
        __syncthreads();
        const __nv_bfloat16* As = smA + (it & 1) * 128 * TSTR;
        const __nv_bfloat16* Bs = smB + (it & 1) * 128 * TSTR;
        #pragma unroll
        for (int ks = 0; ks < 32; ks += 16) {
            uint32_t af[4][4], bfr[4][2];
            int ar = lane >> 2;
            int ac = ks + ((lane & 3) << 1);
            #pragma unroll
            for (int mi = 0; mi < 4; mi++) {
                int r = wm + (mi << 4) + ar;
                af[mi][0] = *(const uint32_t*)(As + r * TSTR + ac);
                af[mi][1] = *(const uint32_t*)(As + (r + 8) * TSTR + ac);
                af[mi][2] = *(const uint32_t*)(As + r * TSTR + ac + 8);
                af[mi][3] = *(const uint32_t*)(As + (r + 8) * TSTR + ac + 8);
            }
            #pragma unroll
            for (int ni = 0; ni < 4; ni++) {
                int nr = wn + (ni << 3) + ar;
                bfr[ni][0] = *(const uint32_t*)(Bs + nr * TSTR + ac);
                bfr[ni][1] = *(const uint32_t*)(Bs + nr * TSTR + ac + 8);
            }
            #pragma unroll
            for (int mi = 0; mi < 4; mi++)
                #pragma unroll
                for (int ni = 0; ni < 4; ni++) mma16816(acc[mi][ni], af[mi], bfr[ni]);
        }
        __syncthreads();
    }

    #pragma unroll
    for (int mi = 0; mi < 4; mi++) {
        int r = wm + (mi << 4) + (lane >> 2);
        bool gr0 = r < a_rows;
        bool gr1 = (r + 8) < a_rows;
        #pragma unroll
        for (int ni = 0; ni < 4; ni++) {
            int cc = wn + (ni << 3) + ((lane & 3) << 1);
            float b0 = colbias ? colbias[cc] : 0.f;
            float b1 = colbias ? colbias[cc + 1] : 0.f;
            float x0 = acc[mi][ni][0] + b0, x1 = acc[mi][ni][1] + b1;
            float y0 = acc[mi][ni][2] + b0, y1 = acc[mi][ni][3] + b1;
            if constexpr (MODE == MODE_RELU_BF16) {
                x0 = fmaxf(x0, 0.f); x1 = fmaxf(x1, 0.f);
                y0 = fmaxf(y0, 0.f); y1 = fmaxf(y1, 0.f);
            }
            if constexpr (MODE == MODE_SIG_F32) {
                x0 = 1.f / (1.f + expf(-x0)); x1 = 1.f / (1.f + expf(-x1));
                y0 = 1.f / (1.f + expf(-y0)); y1 = 1.f / (1.f + expf(-y1));
            }
            if constexpr (MODE == MODE_BF16 || MODE == MODE_RELU_BF16) {
                __nv_bfloat16* Cp = (__nv_bfloat16*)Cout;
                __nv_bfloat162 v0, v1;
                v0.x = __float2bfloat16(x0); v0.y = __float2bfloat16(x1);
                v1.x = __float2bfloat16(y0); v1.y = __float2bfloat16(y1);
                if (gr0) *reinterpret_cast<__nv_bfloat162*>(Cp + (size_t)r * ldc + cc) = v0;
                if (gr1) *reinterpret_cast<__nv_bfloat162*>(Cp + (size_t)(r + 8) * ldc + cc) = v1;
            } else {
                float* Cp = (float*)Cout;
                if (gr0) *reinterpret_cast<float2*>(Cp + (size_t)r * ldc + cc) = make_float2(x0, x1);
                if (gr1) *reinterpret_cast<float2*>(Cp + (size_t)(r + 8) * ldc + cc) = make_float2(y0, y1);
            }
        }
    }
}

// ============ tcgen05 GEMM ============
constexpr uint64_t DESC_BASE_SW128 =
    (uint64_t(2) << 61) | (uint64_t(1) << 46) | (uint64_t(64) << 32) | (uint64_t(1) << 16);
constexpr int TC_SMEM = 99328;

__device__ __forceinline__ uint32_t smem_u32(const void* p) {
    return (uint32_t)__cvta_generic_to_shared(p);
}

#if HAS_TCGEN05
__device__ __forceinline__ void mbar_wait_par(uint32_t addr, uint32_t parity) {
    asm volatile(
        "{\n\t.reg .pred P1;\n\t"
        "LAB_%=: mbarrier.try_wait.parity.acquire.cta.shared::cta.b64 P1, [%0], %1, 0x989680;\n\t"
        "@!P1 bra LAB_%=;\n\t}"
        :: "r"(addr), "r"(parity) : "memory");
}

__device__ __forceinline__ void mma_f16_ss_cg1(uint32_t d, uint64_t ad, uint64_t bd,
                                               uint32_t idesc, uint32_t en) {
    asm volatile(
        "{\n\t.reg .pred p;\n\tsetp.ne.u32 p, %5, 0;\n\t"
        "tcgen05.mma.cta_group::1.kind::f16 [%0], %1, %2, %3, {%4,%4,%4,%4}, p;\n\t}"
        :: "r"(d), "l"(ad), "l"(bd), "r"(idesc), "r"(0u), "r"(en) : "memory");
}

__device__ __forceinline__ void ldtm_x32(uint32_t* r, uint32_t addr) {
    asm volatile(
        "tcgen05.ld.sync.aligned.32x32b.x32.b32 "
        "{%0,%1,%2,%3,%4,%5,%6,%7,%8,%9,%10,%11,%12,%13,%14,%15,"
        "%16,%17,%18,%19,%20,%21,%22,%23,%24,%25,%26,%27,%28,%29,%30,%31}, [%32];"
        : "=r"(r[0]), "=r"(r[1]), "=r"(r[2]), "=r"(r[3]), "=r"(r[4]), "=r"(r[5]),
          "=r"(r[6]), "=r"(r[7]), "=r"(r[8]), "=r"(r[9]), "=r"(r[10]), "=r"(r[11]),
          "=r"(r[12]), "=r"(r[13]), "=r"(r[14]), "=r"(r[15]), "=r"(r[16]), "=r"(r[17]),
          "=r"(r[18]), "=r"(r[19]), "=r"(r[20]), "=r"(r[21]), "=r"(r[22]), "=r"(r[23]),
          "=r"(r[24]), "=r"(r[25]), "=r"(r[26]), "=r"(r[27]), "=r"(r[28]), "=r"(r[29]),
          "=r"(r[30]), "=r"(r[31])
        : "r"(addr));
}

template <int ROWS>
__device__ __forceinline__ void tc_load_tile(int tid, uint32_t sbase,
                                             const __nv_bfloat16* src, int ld, int k0) {
    #pragma unroll
    for (int it = 0; it < ROWS / 32; it++) {
        int u = tid + it * 256;
        int row = u >> 3, c16 = u & 7;
        const void* g = src + (size_t)row * ld + k0 + c16 * 8;
        uint32_t off = row * 128 + c16 * 16;
        uint32_t sw = off ^ ((off >> 3) & 0x70);
        asm volatile("cp.async.cg.shared.global [%0], [%1], 16;\n"
                     :: "r"(sbase + sw), "l"(g) : "memory");
    }
}
#endif

template <int NT, int STAGES, bool OUT_BF16>
__device__ void gemm_tc_body(const __nv_bfloat16* __restrict__ A, int lda,
                             const __nv_bfloat16* __restrict__ Bt, int ldb,
                             void* __restrict__ Cout, int ldc, int K,
                             const float* __restrict__ colbias) {
    extern __shared__ char dsm[];
#if HAS_TCGEN05
    constexpr int A_BYTES = 16384;
    constexpr int STAGE_BYTES = A_BYTES + NT * 128;
    constexpr uint32_t IDESC = (1u << 4) | (1u << 7) | (1u << 10) |
                               ((uint32_t)(NT / 8) << 17) | (8u << 24);
    __shared__ uint64_t s_mbar[STAGES];
    __shared__ uint32_t s_tptr;
    __shared__ float biass[NT];
    int tid = threadIdx.x;
    uint32_t base = (smem_u32(dsm) + 1023) & ~1023u;

    if (tid < 32) {
        asm volatile("tcgen05.alloc.cta_group::1.sync.aligned.shared::cta.b32 [%0], %1;"
                     :: "r"(smem_u32(&s_tptr)), "r"(NT) : "memory");
        asm volatile("tcgen05.relinquish_alloc_permit.cta_group::1.sync.aligned;" ::: "memory");
    }
    if (tid == 0) {
        #pragma unroll
        for (int i = 0; i < STAGES; i++)
            asm volatile("mbarrier.init.shared.b64 [%0], 1;"
                         :: "r"(smem_u32(&s_mbar[i])) : "memory");
    }
    #pragma unroll
    for (int i = tid; i < NT; i += 256) biass[i] = colbias ? colbias[i] : 0.f;
    __syncthreads();
    uint32_t tmem = s_tptr;
    const int S = K >> 6;

    #pragma unroll
    for (int st = 0; st < STAGES - 1; st++) {
        tc_load_tile<128>(tid, base + st * STAGE_BYTES, A, lda, st * 64);
        tc_load_tile<NT>(tid, base + st * STAGE_BYTES + A_BYTES, Bt, ldb, st * 64);
        asm volatile("cp.async.commit_group;\n" ::: "memory");
    }

    for (int s = 0; s < S; s++) {
        if (s + STAGES - 1 < S) {
            if (s >= 1) {
                int u = s - 1;
                mbar_wait_par(smem_u32(&s_mbar[u % STAGES]), (uint32_t)((u / STAGES) & 1));
            }
            int b = (s + STAGES - 1) % STAGES;
            tc_load_tile<128>(tid, base + b * STAGE_BYTES, A, lda, (s + STAGES - 1) * 64);
            tc_load_tile<NT>(tid, base + b * STAGE_BYTES + A_BYTES, Bt, ldb,
                             (s + STAGES - 1) * 64);
        }
        asm volatile("cp.async.commit_group;\n" ::: "memory");
        asm volatile("cp.async.wait_group %0;\n" :: "n"(STAGES - 1) : "memory");
        __syncthreads();
        asm volatile("fence.proxy.async.shared::cta;" ::: "memory");
        if (tid == 0) {
            int b = s % STAGES;
            uint64_t ad = DESC_BASE_SW128 |
                          ((uint64_t)((base + b * STAGE_BYTES) >> 4) & 0x3FFF);
            uint64_t bd = DESC_BASE_SW128 |
                          ((uint64_t)((base + b * STAGE_BYTES + A_BYTES) >> 4) & 0x3FFF);
            #pragma unroll
            for (int q = 0; q < 4; q++)
                mma_f16_ss_cg1(tmem, ad + q * 2, bd + q * 2, IDESC,
                               (s > 0 || q > 0) ? 1u : 0u);
            asm volatile(
                "tcgen05.commit.cta_group::1.mbarrier::arrive::one.shared::cluster.b64 [%0];"
                :: "r"(smem_u32(&s_mbar[b])) : "memory");
        }
    }
    {
        int u = S - 1;
        mbar_wait_par(smem_u32(&s_mbar[u % STAGES]), (uint32_t)((u / STAGES) & 1));
    }
    asm volatile("tcgen05.fence::after_thread_sync;" ::: "memory");

    int w = tid >> 5, lane = tid & 31;
    int row = (w & 3) * 32 + lane;
    int colbase = (w >> 2) * (NT / 2);

    if constexpr (OUT_BF16) {
        constexpr int OSTR = NT + 24;
        __nv_bfloat16* so = (__nv_bfloat16*)(dsm + (base - smem_u32(dsm)));
        __syncthreads();
        #pragma unroll
        for (int half = 0; half < NT / 64; half++) {
            int cb = colbase + half * 32;
            uint32_t r[32];
            ldtm_x32(r, tmem + cb);
            asm volatile("tcgen05.wait::ld.sync.aligned;" ::: "memory");
            #pragma unroll
            for (int j = 0; j < 32; j += 2) {
                __nv_bfloat162 h;
                h.x = __float2bfloat16(__uint_as_float(r[j]) + biass[cb + j]);
                h.y = __float2bfloat16(__uint_as_float(r[j + 1]) + biass[cb + j + 1]);
                *reinterpret_cast<__nv_bfloat162*>(so + row * OSTR + cb + j) = h;
            }
        }
        __syncthreads();
        constexpr int CH = NT / 8;
        __nv_bfloat16* Cp = (__nv_bfloat16*)Cout;
        #pragma unroll
        for (int u = tid; u < 128 * CH; u += 256) {
            int rr = u / CH, cc = (u - rr * CH) * 8;
            uint4 v = *reinterpret_cast<const uint4*>(so + rr * OSTR + cc);
            *reinterpret_cast<uint4*>(Cp + (size_t)rr * ldc + cc) = v;
        }
    } else {
        #pragma unroll
        for (int half = 0; half < NT / 64; half++) {
            int cb = colbase + half * 32;
            uint32_t r[32];
            ldtm_x32(r, tmem + cb);
            asm volatile("tcgen05.wait::ld.sync.aligned;" ::: "memory");
            float* Cp = (float*)Cout;
            #pragma unroll
            for (int j = 0; j < 32; j += 4) {
                float4 v;
                v.x = __uint_as_float(r[j]) + biass[cb + j];
                v.y = __uint_as_float(r[j + 1]) + biass[cb + j + 1];
                v.z = __uint_as_float(r[j + 2]) + biass[cb + j + 2];
                v.w = __uint_as_float(r[j + 3]) + biass[cb + j + 3];
                *reinterpret_cast<float4*>(Cp + (size_t)row * ldc + cb + j) = v;
            }
        }
    }
    __syncthreads();
    if (tid < 32)
        asm volatile("tcgen05.dealloc.cta_group::1.sync.aligned.b32 %0, %1;"
                     :: "r"(tmem), "r"(NT));
#else
    __nv_bfloat16* smA = (__nv_bfloat16*)dsm;
    __nv_bfloat16* smB = smA + 2 * 128 * TSTR;
    #pragma unroll
    for (int nt2 = 0; nt2 < NT / 128; nt2++) {
        if (nt2 > 0) __syncthreads();
        if constexpr (OUT_BF16)
            gemm_cp_body<MODE_BF16>(smA, smB, A, lda, 128, Bt + (size_t)nt2 * 128 * ldb, ldb,
                                    (__nv_bfloat16*)Cout + nt2 * 128, ldc, K,
                                    colbias ? colbias + nt2 * 128 : nullptr);
        else
            gemm_cp_body<MODE_F32>(smA, smB, A, lda, 128, Bt + (size_t)nt2 * 128 * ldb, ldb,
                                   (float*)Cout + nt2 * 128, ldc, K,
                                   colbias ? colbias + nt2 * 128 : nullptr);
    }
#endif
}

__global__ void __launch_bounds__(256) gemm_qk_tc_kernel() {
    int z = blockIdx.z;
    int p = z >> 1, s = z & 1;
    const __nv_bfloat16* A = g_XdT + ((size_t)p * BN_ + (size_t)blockIdx.x * 128) * C_;
    const __nv_bfloat16* Bt = (s ? g_Wk : g_Wq) + (size_t)p * IC_ * C_;
    __nv_bfloat16* Cm = (s ? g_KT : g_QT) + ((size_t)p * BN_ + (size_t)blockIdx.x * 128) * IC_;
    const float* cb = (s ? g_kbias : g_qbias) + p * IC_;
    gemm_tc_body<128, 3, true>(A, C_, Bt, C_, Cm, IC_, C_, cb);
}

__global__ void __launch_bounds__(256) gemm_v_tc_kernel(const float* __restrict__ vb) {
    int p = blockIdx.z;
    const __nv_bfloat16* A = g_MT + ((size_t)p * BN_ + (size_t)blockIdx.x * 128) * C_;
    const __nv_bfloat16* Bt = g_Wv + ((size_t)p * C_ + (size_t)blockIdx.y * 256) * C_;
    __nv_bfloat16* Cm = g_AOT + ((size_t)p * BN_ + (size_t)blockIdx.x * 128) * C_ + blockIdx.y * 256;
    gemm_tc_body<256, 2, true>(A, C_, Bt, C_, Cm, C_, C_, vb + p * C_ + blockIdx.y * 256);
}

// MT via HMMA (K=96)
__global__ void __launch_bounds__(256, 2) gemm_m_kernel() {
    __shared__ __nv_bfloat16 smA[2][128 * TSTR];
    __shared__ __nv_bfloat16 smB[2][128 * TSTR];
    int z = blockIdx.z;
    int b = z / P_, p = z % P_;
    const __nv_bfloat16* A = g_attn + (size_t)z * N_ * N_;
    const __nv_bfloat16* Bt = g_Xd + ((size_t)p * C_ + (size_t)blockIdx.x * 128) * BN_ + b * N_;
    __nv_bfloat16* Cm = g_MT + ((size_t)p * BN_ + b * N_) * C_ + blockIdx.x * 128;
    gemm_cp_body<MODE_BF16>(&smA[0][0], &smB[0][0], A, N_, N_, Bt, BN_, Cm, C_, N_, nullptr);
}

// ---------------- attention ----------------
__global__ void __launch_bounds__(256) attn_kernel() {
    int bp = blockIdx.x;
    int b = bp / P_, p = bp % P_;
    __shared__ __nv_bfloat16 qs[IC_ * N_];
    __shared__ __nv_bfloat16 ks[IC_ * N_];
    int t = threadIdx.x;
    const __nv_bfloat16* qt = g_QT + ((size_t)p * BN_ + b * N_) * IC_;
    const __nv_bfloat16* kt = g_KT + ((size_t)p * BN_ + b * N_) * IC_;
    for (int u = t; u < IC_ * N_; u += 256) {
        int n = u >> 7, i = u & 127;
        qs[i * N_ + n] = qt[n * IC_ + i];
        ks[i * N_ + n] = kt[n * IC_ + i];
    }
    __syncthreads();
    int wid = t >> 5, lane = t & 31;
    size_t ab = (size_t)bp * N_ * N_;
    for (int n = wid; n < N_; n += 8) {
        float e0 = 0.f, e1 = 0.f, e2 = 0.f;
        for (int i = 0; i < IC_; i++) {
            float qv = __bfloat162float(qs[i * N_ + n]);
            e0 += qv * __bfloat162float(ks[i * N_ + lane]);
            e1 += qv * __bfloat162float(ks[i * N_ + lane + 32]);
            e2 += qv * __bfloat162float(ks[i * N_ + lane + 64]);
        }
        float mx = fmaxf(e0, fmaxf(e1, e2));
        #pragma unroll
        for (int o = 16; o; o >>= 1) mx = fmaxf(mx, __shfl_xor_sync(0xffffffffu, mx, o));
        float s0 = expf(e0 - mx), s1 = expf(e1 - mx), s2 = expf(e2 - mx);
        float ss = s0 + s1 + s2;
        #pragma unroll
        for (int o = 16; o; o >>= 1) ss += __shfl_xor_sync(0xffffffffu, ss, o);
        float inv = 1.f / ss;
        g_attn[ab + (size_t)n * N_ + lane] = __float2bfloat16(s0 * inv);
        g_attn[ab + (size_t)n * N_ + lane + 32] = __float2bfloat16(s1 * inv);
        g_attn[ab + (size_t)n * N_ + lane + 64] = __float2bfloat16(s2 * inv);
    }
}

// ---------------- gap reduce ----------------
__global__ void __launch_bounds__(512) gap_kernel(const float* __restrict__ pa_gamma) {
    int bp = blockIdx.x;
    int b = bp / P_, p = bp % P_;
    int t = threadIdx.x;
    float gam = pa_gamma[p];
    const __nv_bfloat16* aob = g_AOT + ((size_t)p * BN_ + b * N_) * C_;
    for (int c = t; c < C_; c += 512) {
        float acc = 0.f;
        #pragma unroll 8
        for (int n = 0; n < N_; n++) acc += __bfloat162float(aob[(size_t)n * C_ + c]);
        float g = gam * (acc * (1.f / N_)) + g_meanXd[((size_t)b * P_ + p) * C_ + c];
        g_gap[((size_t)p * B_ + b) * C_ + c] = __float2bfloat16(g);
    }
}

// ---------------- MLP ----------------
__global__ void __launch_bounds__(256) mlp1_kernel(const float* __restrict__ fc1b) {
    __shared__ __nv_bfloat16 smA[2][128 * TSTR];
    __shared__ __nv_bfloat16 smB[2][128 * TSTR];
    int p = blockIdx.z;
    const __nv_bfloat16* A = g_gap + (size_t)p * B_ * C_;
    const __nv_bfloat16* Bt = g_Wfc1 + ((size_t)p * C4_ + blockIdx.x * 128) * C_;
    __nv_bfloat16* Cm = g_h1 + (size_t)p * B_ * C4_ + blockIdx.x * 128;
    gemm_cp_body<MODE_RELU_BF16>(&smA[0][0], &smB[0][0], A, C_, B_, Bt, C_, Cm, C4_, C_,
                                 fc1b + p * C4_ + blockIdx.x * 128);
}

__global__ void __launch_bounds__(256) mlp2_kernel(const float* __restrict__ fc2b) {
    __shared__ __nv_bfloat16 smA[2][128 * TSTR];
    __shared__ __nv_bfloat16 smB[2][128 * TSTR];
    int p = blockIdx.z;
    const __nv_bfloat16* A = g_h1 + (size_t)p * B_ * C4_;
    const __nv_bfloat16* Bt = g_Wfc2 + ((size_t)p * C_ + blockIdx.x * 128) * C4_;
    float* Cm = g_cw + (size_t)p * C_ + blockIdx.x * 128;
    gemm_cp_body<MODE_SIG_F32>(&smA[0][0], &smB[0][0], A, C4_, B_, Bt, C4_, Cm, P_ * C_, C4_,
                               fc2b + p * C_ + blockIdx.x * 128);
}

// ---------------- fused upsample + pa/ca/gate + output ----------------
__global__ void __launch_bounds__(384) final_kernel(
    const float* __restrict__ x, float* __restrict__ out,
    const float* __restrict__ pa_gamma, const float* __restrict__ ca_gamma,
    const int* __restrict__ modality,
    const float* __restrict__ gw1, const float* __restrict__ gb1,
    const float* __restrict__ gw2, const float* __restrict__ gb2) {
    int cb = blockIdx.x;
    int p = blockIdx.y, b = blockIdx.z;
    __shared__ float aos[16][97];
    __shared__ float cws[16];
    int t = threadIdx.x;
    int c0 = cb * 16;
    const __nv_bfloat16* aob = g_AOT + ((size_t)p * BN_ + b * N_) * C_ + c0;
    for (int u = t; u < 16 * N_; u += 384) {
        int n = u >> 4, ch = u & 15;
        aos[ch][n] = __bfloat162float(aob[(size_t)n * C_ + ch]);
    }
    if (t < 16) cws[t] = g_cw[((size_t)b * P_ + p) * C_ + c0 + t];
    __syncthreads();

    float mf = (float)modality[b];
    float gacc = gb2[p];
    #pragma unroll
    for (int j = 0; j < 12; j++)
        gacc += fmaxf(mf * gw1[j] + gb1[j], 0.f) * gw2[p * 12 + j];
    float wgt = 1.f / (1.f + expf(-gacc));

    int ph = t / W_, w = t % W_;
    float srcr = 0.5f * ph - 0.25f;
    int ri = (int)floorf(srcr);
    float fr = srcr - ri;
    int ra = ri, rb = ri + 1;
    float wra = 1.f - fr, wrb = fr;
    if (ra < 0) { ra = 0; wra = 0.f; }
    if (rb > HD_ - 1) { rb = HD_ - 1; wrb = 0.f; }
    { float s = wra + wrb; wra /= s; wrb /= s; }
    float srcc = 0.5f * w - 0.25f;
    int ci = (int)floorf(srcc);
    float fc = srcc - ci;
    int ca = ci, cbx = ci + 1;
    float wca = 1.f - fc, wcb = fc;
    if (ca < 0) { ca = 0; wca = 0.f; }
    if (cbx > WD_ - 1) { cbx = WD_ - 1; wcb = 0.f; }
    { float s = wca + wcb; wca /= s; wcb /= s; }

    float pg = pa_gamma[p], cg = ca_gamma[p];

    #pragma unroll 4
    for (int ch = 0; ch < 16; ch++) {
        int c = c0 + ch;
        float up = wra * (wca * aos[ch][ra * WD_ + ca] + wcb * aos[ch][ra * WD_ + cbx]) +
                   wrb * (wca * aos[ch][rb * WD_ + ca] + wcb * aos[ch][rb * WD_ + cbx]);
        size_t xi = (((size_t)b * C_ + c) * H_ + p * PH_ + ph) * W_ + w;
        float xp = x[xi];
        float pa = pg * up + xp;
        float res = xp * (1.f - wgt) + wgt * pa * (1.f + cg * cws[ch]);
        out[xi] = res;
    }
}

extern "C" void kernel_launch(void* const* d_in, const int* in_sizes, int n_in,
                              void* d_out, int out_size) {
    const float* x = (const float*)d_in[0];
    cudaFuncSetAttribute(gemm_qk_tc_kernel, cudaFuncAttributeMaxDynamicSharedMemorySize, TC_SMEM);
    cudaFuncSetAttribute(gemm_v_tc_kernel, cudaFuncAttributeMaxDynamicSharedMemorySize, TC_SMEM);

    fold_qk_kernel<<<2 * P_ * IC_, 256>>>(
        (const float*)d_in[3], (const float*)d_in[1], (const float*)d_in[2], (const float*)d_in[4],
        (const float*)d_in[7], (const float*)d_in[5], (const float*)d_in[6], (const float*)d_in[8]);
    conv_weights_kernel<<<2048, 256>>>((const float*)d_in[9],
                                       (const float*)d_in[12], (const float*)d_in[14]);
    pool_kernel<<<B_ * C_, 288>>>(x);
    transpose_xd_kernel<<<dim3(BN_ / 64, C_ / 64, P_), 256>>>();
    gemm_qk_tc_kernel<<<dim3(BN_ / 128, 1, 2 * P_), 256, TC_SMEM>>>();
    attn_kernel<<<B_ * P_, 256>>>();
    gemm_m_kernel<<<dim3(C_ / 128, 1, B_ * P_), 256>>>();
    gemm_v_tc_kernel<<<dim3(BN_ / 128, C_ / 256, P_), 256, TC_SMEM>>>((const float*)d_in[10]);
    gap_kernel<<<B_ * P_, 512>>>((const float*)d_in[11]);
    mlp1_kernel<<<dim3(C4_ / 128, 1, P_), 256>>>((const float*)d_in[13]);
    mlp2_kernel<<<dim3(C_ / 128, 1, P_), 256>>>((const float*)d_in[15]);
    final_kernel<<<dim3(C_ / 16, P_, B_), 384>>>(x, (float*)d_out,
        (const float*)d_in[11], (const float*)d_in[16],
        (const int*)d_in[21],
        (const float*)d_in[17], (const float*)d_in[18],
        (const float*)d_in[19], (const float*)d_in[20]);
}